// round 14
// baseline (speedup 1.0000x reference)
#include <cuda_runtime.h>
#include <cuda_fp16.h>
#include <cuda_bf16.h>
#include <cstdint>

#define OUT_F 8192
#define IN_F  8192
#define TOKENS 256
#define KPAD  8256          // 8192 + 16 lora cols + 48 zero pad
#define NITER 129           // KPAD / 64

// Scratch (device globals — no cudaMalloc allowed)
__device__ __half g_xh[(size_t)TOKENS * KPAD];  // x fp16 | t1 fp16 | zeros
__device__ int g_wn_mode;                       // 0=f32, 1=f16, 2=bf16

__device__ __forceinline__ uint32_t smem_u32(const void* p) {
    uint32_t a;
    asm("{ .reg .u64 t; cvta.to.shared.u64 t, %1; cvt.u32.u64 %0, t; }" : "=r"(a) : "l"(p));
    return a;
}

// ---------------- prep: t1 (first, long poles) + xconv + probe -------------
#define T1_BLOCKS 256
#define XC_BLOCKS 1030
#define PREP_BLOCKS (T1_BLOCKS + XC_BLOCKS + 1)

__global__ void __launch_bounds__(256) qlora_prep(const float* __restrict__ x,
                                                  const float* __restrict__ la,
                                                  const void* __restrict__ wn) {
    const int blk = blockIdx.x;
    if (blk < T1_BLOCKS) {
        // ---- t1: token = block; warp w handles lora rows 2w, 2w+1 ----
        const int t = blk;
        const int w = threadIdx.x >> 5;
        const int lid = threadIdx.x & 31;
        const float* xrow = x + (size_t)t * IN_F;
        const float* a0 = la + (size_t)(2 * w) * IN_F;
        const float* a1 = la + (size_t)(2 * w + 1) * IN_F;
        float s0 = 0.f, s1 = 0.f;
        for (int i = 0; i < 64; i++) {
            int k = i * 128 + lid * 4;
            float4 xv = *(const float4*)(xrow + k);
            float4 v0 = __ldg((const float4*)(a0 + k));
            float4 v1 = __ldg((const float4*)(a1 + k));
            s0 += xv.x * v0.x + xv.y * v0.y + xv.z * v0.z + xv.w * v0.w;
            s1 += xv.x * v1.x + xv.y * v1.y + xv.z * v1.z + xv.w * v1.w;
        }
#pragma unroll
        for (int s = 16; s; s >>= 1) {
            s0 += __shfl_xor_sync(0xFFFFFFFFu, s0, s);
            s1 += __shfl_xor_sync(0xFFFFFFFFu, s1, s);
        }
        if (lid == 0) {
            g_xh[(size_t)t * KPAD + 8192 + 2 * w]     = __float2half_rn(s0);
            g_xh[(size_t)t * KPAD + 8192 + 2 * w + 1] = __float2half_rn(s1);
        }
    } else if (blk < T1_BLOCKS + XC_BLOCKS) {
        // ---- xconv: x f32 -> g_xh fp16, + zero pad cols [8208,8256) ----
        int tid = (blk - T1_BLOCKS) * 256 + threadIdx.x;
        const int MAIN = TOKENS * IN_F / 8;  // 262144
        if (tid < MAIN) {
            int e = tid << 3;
            int t = e >> 13, i = e & 8191;
            float4 f0 = *(const float4*)(x + e);
            float4 f1 = *(const float4*)(x + e + 4);
            __half2 h0 = __floats2half2_rn(f0.x, f0.y);
            __half2 h1 = __floats2half2_rn(f0.z, f0.w);
            __half2 h2 = __floats2half2_rn(f1.x, f1.y);
            __half2 h3 = __floats2half2_rn(f1.z, f1.w);
            uint4 v;
            v.x = *(uint32_t*)&h0; v.y = *(uint32_t*)&h1;
            v.z = *(uint32_t*)&h2; v.w = *(uint32_t*)&h3;
            *(uint4*)(g_xh + (size_t)t * KPAD + i) = v;
        } else {
            int p = tid - MAIN;
            if (p < TOKENS * 6) {
                int t = p / 6, u = p % 6;
                uint4 z = {0u, 0u, 0u, 0u};
                *(uint4*)(g_xh + (size_t)t * KPAD + 8208 + u * 8) = z;
            }
        }
    } else {
        // ---- probe: parallel wn-dtype classify (g_wn_mode used by GEMM only)
        __shared__ int cnt[2];
        if (threadIdx.x < 2) cnt[threadIdx.x] = 0;
        __syncthreads();
        if (threadIdx.x < 128) {
            float f = __uint_as_float(((const uint32_t*)wn)[threadIdx.x]);
            if (f > 0.004f && f < 1.05f) atomicAdd(&cnt[0], 1);
        }
        {
            uint16_t h = ((const uint16_t*)wn)[threadIdx.x];
            if (h < 0x3C08u) atomicAdd(&cnt[1], 1);
        }
        __syncthreads();
        if (threadIdx.x == 0) {
            if (cnt[0] >= 100)      g_wn_mode = 0;
            else if (cnt[1] >= 128) g_wn_mode = 1;
            else                    g_wn_mode = 2;
        }
    }
}

// ---------------- GEMM: fused dequant, CTA tile 256(M) x 64(N) -------------
// grid (128, 1) = 128 CTAs, 1 CTA/SM, 256 threads / 8 warps.
// Warp grid 8(M) x 1(N): warp tile 32x64, acc 64 regs.
// B decode per CTA HALVED vs R11 (64 rows, each decoded exactly once grid-wide).
#define ROWP 72
#define ATILE_B (256 * ROWP * 2)      // 36864 bytes
#define BTILE_B (64 * ROWP * 2)       // 9216 bytes
#define SM_A 0                        // 3 A buffers
#define SM_B (3 * ATILE_B)            // 110592: 2 B buffers
#define SM_SEL (SM_B + 2 * BTILE_B)   // 129024: PRMT selector table
#define GEMM_SMEM (SM_SEL + 1024)     // 130048

__device__ __forceinline__ void mma16816(float& c0, float& c1, float& c2, float& c3,
                                         uint32_t a0, uint32_t a1, uint32_t a2, uint32_t a3,
                                         uint32_t b0, uint32_t b1) {
    asm volatile("mma.sync.aligned.m16n8k16.row.col.f32.f16.f16.f32 "
                 "{%0,%1,%2,%3}, {%4,%5,%6,%7}, {%8,%9}, {%0,%1,%2,%3};"
                 : "+f"(c0), "+f"(c1), "+f"(c2), "+f"(c3)
                 : "r"(a0), "r"(a1), "r"(a2), "r"(a3), "r"(b0), "r"(b1));
}

__device__ __forceinline__ float load_norm(const void* wn, int g, int mode) {
    if (mode == 0) return ((const float*)wn)[g];
    if (mode == 1) return __half2float(((const __half*)wn)[g]);
    return __bfloat162float(((const __nv_bfloat16*)wn)[g]);
}

__global__ void __launch_bounds__(256, 1) qlora_gemm(const int* __restrict__ q2,
                                                     const void* __restrict__ wn,
                                                     const float* __restrict__ lb,
                                                     const float* __restrict__ bias,
                                                     float* __restrict__ out) {
    extern __shared__ char smem[];
    const uint32_t sb = smem_u32(smem);
    const int tid = threadIdx.x;
    const int wid = tid >> 5;        // warp M index 0..7 (32 rows each)
    const int lid = tid & 31;
    const int bx = blockIdx.x;       // N tile 0..127 (64 cols)
    const int fr = lid >> 2;
    const int fc = (lid & 3) << 1;
    const int mode = g_wn_mode;

    uint32_t* selt = (uint32_t*)(smem + SM_SEL);
    {
        int b = tid;
        selt[b] = (uint32_t)((b & 3) | (((b >> 2) & 3) << 4) |
                             (((b >> 4) & 3) << 8) | (((b >> 6) & 3) << 12));
    }

    // B decode: 4 threads per row (64 rows); each thread 4 int32 = 16 codes/iter
    const int brow = tid >> 2;       // 0..63
    const int hs = tid & 3;
    const int o = bx * 64 + brow;
    const int* crow = q2 + (size_t)o * 2048;

    // A producer: 256 rows, 1 thread/row, 128B (64 halves) per iter
    const __half* Ag = g_xh + (size_t)tid * KPAD;
    const uint32_t a_off = (uint32_t)tid * (ROWP * 2);

    auto issueA = [&](int buf3, int kk) {
        uint32_t dst = sb + SM_A + buf3 * ATILE_B + a_off;
        const char* src = (const char*)(Ag + kk);
#pragma unroll
        for (int u = 0; u < 8; u++)
            asm volatile("cp.async.cg.shared.global [%0], [%1], 16;"
                         :: "r"(dst + u * 16), "l"(src + u * 16) : "memory");
    };

    // decode 4 int32 codes (C0) with norm n -> 8 u32 halves -> STS (32B)
    auto decodeSTS = [&](int j, uint4 C0, uint4 C1, float n) {
        uint32_t r[8];
        if (j < 128) {
            float n3 = n * 0.33333334f;
            __half h0 = __float2half_rn(-n),  h1 = __float2half_rn(-n3);
            __half h2 = __float2half_rn(n3),  h3 = __float2half_rn(n);
            uint32_t p01 = (uint32_t)__half_as_ushort(h0) | ((uint32_t)__half_as_ushort(h1) << 16);
            uint32_t p23 = (uint32_t)__half_as_ushort(h2) | ((uint32_t)__half_as_ushort(h3) << 16);
            uint32_t t_lo = __byte_perm(p01, p23, 0x6420);
            uint32_t t_hi = __byte_perm(p01, p23, 0x7531);
            uint32_t w[4] = {C0.x, C0.y, C0.z, C0.w};
#pragma unroll
            for (int i = 0; i < 4; i++) {
                uint32_t sel = selt[w[i] & 0xFF];
                uint32_t lo4 = __byte_perm(t_lo, 0u, sel);
                uint32_t hi4 = __byte_perm(t_hi, 0u, sel);
                r[2 * i]     = __byte_perm(lo4, hi4, 0x5140);
                r[2 * i + 1] = __byte_perm(lo4, hi4, 0x7362);
            }
        } else {
            // j == 128: cols 0-15 = lora_b (hs==0), rest of 64-col pad = 0
#pragma unroll
            for (int i = 0; i < 8; i++) r[i] = 0u;
            if (hs == 0) {
                r[0] = C0.x; r[1] = C0.y; r[2] = C0.z; r[3] = C0.w;
                r[4] = C1.x; r[5] = C1.y; r[6] = C1.z; r[7] = C1.w;
            }
        }
        char* dst = smem + SM_B + (j & 1) * BTILE_B + brow * (ROWP * 2) + hs * 32;
        *(uint4*)(dst)      = make_uint4(r[0], r[1], r[2], r[3]);
        *(uint4*)(dst + 16) = make_uint4(r[4], r[5], r[6], r[7]);
    };

    auto loadCodes = [&](int j, uint4& C0, uint4& C1, float& n) {
        if (j < 128) {
            C0 = __ldg((const uint4*)(crow + j * 16 + hs * 4));
            n = load_norm(wn, o * 64 + (j >> 1), mode);
        } else if (hs == 0) {
            const float4* s = (const float4*)(lb + (size_t)o * 16);
            float4 f0 = __ldg(s), f1 = __ldg(s + 1), f2 = __ldg(s + 2), f3 = __ldg(s + 3);
            __half2 a0 = __floats2half2_rn(f0.x, f0.y), a1 = __floats2half2_rn(f0.z, f0.w);
            __half2 a2 = __floats2half2_rn(f1.x, f1.y), a3 = __floats2half2_rn(f1.z, f1.w);
            __half2 a4 = __floats2half2_rn(f2.x, f2.y), a5 = __floats2half2_rn(f2.z, f2.w);
            __half2 a6 = __floats2half2_rn(f3.x, f3.y), a7 = __floats2half2_rn(f3.z, f3.w);
            C0 = make_uint4(*(uint32_t*)&a0, *(uint32_t*)&a1, *(uint32_t*)&a2, *(uint32_t*)&a3);
            C1 = make_uint4(*(uint32_t*)&a4, *(uint32_t*)&a5, *(uint32_t*)&a6, *(uint32_t*)&a7);
        }
    };

    float acc[2][8][4];
#pragma unroll
    for (int mi = 0; mi < 2; mi++)
#pragma unroll
        for (int ni = 0; ni < 8; ni++)
#pragma unroll
            for (int r = 0; r < 4; r++) acc[mi][ni][r] = 0.f;

    uint4 C0 = {0, 0, 0, 0}, C1 = {0, 0, 0, 0};
    float cn = 0.f;
    loadCodes(0, C0, C1, cn);
    __syncthreads();
    decodeSTS(0, C0, C1, cn);
    issueA(0, 0);  asm volatile("cp.async.commit_group;" ::: "memory");
    issueA(1, 64); asm volatile("cp.async.commit_group;" ::: "memory");
    loadCodes(1, C0, C1, cn);
    __syncthreads();

    int abuf = 0;
    for (int it = 0; it < NITER; it++) {
        asm volatile("cp.async.wait_group 1;" ::: "memory");
        __syncthreads();

        const __half* As = (const __half*)(smem + SM_A + abuf * ATILE_B);
        const __half* Bs = (const __half*)(smem + SM_B + (it & 1) * BTILE_B);

#pragma unroll
        for (int ks = 0; ks < 2; ks++) {
            const int kb = ks * 16;
            uint32_t a[2][4];
#pragma unroll
            for (int mi = 0; mi < 2; mi++) {
                const __half* ap = As + (wid * 32 + mi * 16 + fr) * ROWP + kb + fc;
                a[mi][0] = *(const uint32_t*)(ap);
                a[mi][1] = *(const uint32_t*)(ap + 8 * ROWP);
                a[mi][2] = *(const uint32_t*)(ap + 8);
                a[mi][3] = *(const uint32_t*)(ap + 8 * ROWP + 8);
            }
#pragma unroll
            for (int ni = 0; ni < 8; ni++) {
                const __half* bp = Bs + (ni * 8 + fr) * ROWP + kb + fc;
                uint32_t b0 = *(const uint32_t*)(bp);
                uint32_t b1 = *(const uint32_t*)(bp + 8);
#pragma unroll
                for (int mi = 0; mi < 2; mi++)
                    mma16816(acc[mi][ni][0], acc[mi][ni][1], acc[mi][ni][2], acc[mi][ni][3],
                             a[mi][0], a[mi][1], a[mi][2], a[mi][3], b0, b1);
            }
        }

        if (it <= 127) decodeSTS(it + 1, C0, C1, cn);
        if (it + 2 <= 128) loadCodes(it + 2, C0, C1, cn);
        if (it + 2 < NITER) {
            int nb = abuf + 2; if (nb >= 3) nb -= 3;
            issueA(nb, (it + 2) * 64);
        }
        asm volatile("cp.async.commit_group;" ::: "memory");

#pragma unroll
        for (int ks = 2; ks < 4; ks++) {
            const int kb = ks * 16;
            uint32_t a[2][4];
#pragma unroll
            for (int mi = 0; mi < 2; mi++) {
                const __half* ap = As + (wid * 32 + mi * 16 + fr) * ROWP + kb + fc;
                a[mi][0] = *(const uint32_t*)(ap);
                a[mi][1] = *(const uint32_t*)(ap + 8 * ROWP);
                a[mi][2] = *(const uint32_t*)(ap + 8);
                a[mi][3] = *(const uint32_t*)(ap + 8 * ROWP + 8);
            }
#pragma unroll
            for (int ni = 0; ni < 8; ni++) {
                const __half* bp = Bs + (ni * 8 + fr) * ROWP + kb + fc;
                uint32_t b0 = *(const uint32_t*)(bp);
                uint32_t b1 = *(const uint32_t*)(bp + 8);
#pragma unroll
                for (int mi = 0; mi < 2; mi++)
                    mma16816(acc[mi][ni][0], acc[mi][ni][1], acc[mi][ni][2], acc[mi][ni][3],
                             a[mi][0], a[mi][1], a[mi][2], a[mi][3], b0, b1);
            }
        }

        abuf++; if (abuf == 3) abuf = 0;
    }
    asm volatile("cp.async.wait_group 0;" ::: "memory");

    // epilogue: warp wid owns rows wid*32 + {fr, fr+8, +16, +24}; cols bx*64..
    const int m0 = wid * 32 + fr;
    const int n00 = bx * 64 + fc;
#pragma unroll
    for (int mi = 0; mi < 2; mi++) {
#pragma unroll
        for (int ni = 0; ni < 8; ni++) {
            int n = n00 + ni * 8;
            float b0 = __ldg(bias + n), b1 = __ldg(bias + n + 1);
            int mA = m0 + mi * 16;
            float2 v0 = {acc[mi][ni][0] + b0, acc[mi][ni][1] + b1};
            float2 v1 = {acc[mi][ni][2] + b0, acc[mi][ni][3] + b1};
            *(float2*)(out + (size_t)mA * OUT_F + n) = v0;
            *(float2*)(out + (size_t)(mA + 8) * OUT_F + n) = v1;
        }
    }
}

// ---------------- launch ----------------
extern "C" void kernel_launch(void* const* d_in, const int* in_sizes, int n_in,
                              void* d_out, int out_size) {
    int ix = -1, iq = -1, iwn = -1, ib = -1, ila = -1, ilb = -1;
    for (int i = 0; i < n_in; i++) {
        int s = in_sizes[i];
        if (s == TOKENS * IN_F)            ix = i;
        else if (s == OUT_F * IN_F / 4)    iq = i;
        else if (s == OUT_F * IN_F / 128)  iwn = i;
        else if (s == OUT_F)               ib = i;
        else if (s == 16 * IN_F)           { if (ila < 0) ila = i; else ilb = i; }
    }
    const float* x    = (const float*)d_in[ix];
    const int*   q2   = (const int*)d_in[iq];
    const void*  wn   = (const void*)d_in[iwn];
    const float* bias = (const float*)d_in[ib];
    const float* la   = (const float*)d_in[ila];
    const float* lb   = (const float*)d_in[ilb];
    float* out = (float*)d_out;

    qlora_prep<<<PREP_BLOCKS, 256>>>(x, la, wn);

    cudaFuncSetAttribute(qlora_gemm, cudaFuncAttributeMaxDynamicSharedMemorySize, GEMM_SMEM);
    qlora_gemm<<<dim3(128, 1), 256, GEMM_SMEM>>>(q2, wn, lb, bias, out);
}

// round 15
// speedup vs baseline: 2.0488x; 2.0488x over previous
#include <cuda_runtime.h>
#include <cuda_fp16.h>
#include <cuda_bf16.h>
#include <cstdint>

#define OUT_F 8192
#define IN_F  8192
#define TOKENS 256
#define KPAD  8256          // 8192 + 16 lora cols + 48 zero pad
#define NITER 129           // KPAD / 64

// Scratch (device globals — no cudaMalloc allowed)
__device__ __half g_xh[(size_t)TOKENS * KPAD];  // x fp16 | t1 fp16 | zeros
__device__ int g_wn_mode;                       // 0=f32, 1=f16, 2=bf16

__device__ __forceinline__ uint32_t smem_u32(const void* p) {
    uint32_t a;
    asm("{ .reg .u64 t; cvta.to.shared.u64 t, %1; cvt.u32.u64 %0, t; }" : "=r"(a) : "l"(p));
    return a;
}

// ---------------- prep: t1 (long poles first) + xconv + probe --------------
#define T1_BLOCKS 256
#define XC_BLOCKS 1030
#define PREP_BLOCKS (T1_BLOCKS + XC_BLOCKS + 1)

__global__ void __launch_bounds__(256) qlora_prep(const float* __restrict__ x,
                                                  const float* __restrict__ la,
                                                  const void* __restrict__ wn) {
    const int blk = blockIdx.x;
    if (blk < T1_BLOCKS) {
        // ---- t1: token = block; warp w handles lora rows 2w, 2w+1 ----
        const int t = blk;
        const int w = threadIdx.x >> 5;
        const int lid = threadIdx.x & 31;
        const float* xrow = x + (size_t)t * IN_F;
        const float* a0 = la + (size_t)(2 * w) * IN_F;
        const float* a1 = la + (size_t)(2 * w + 1) * IN_F;
        float s0 = 0.f, s1 = 0.f;
        for (int i = 0; i < 64; i++) {
            int k = i * 128 + lid * 4;
            float4 xv = *(const float4*)(xrow + k);
            float4 v0 = __ldg((const float4*)(a0 + k));
            float4 v1 = __ldg((const float4*)(a1 + k));
            s0 += xv.x * v0.x + xv.y * v0.y + xv.z * v0.z + xv.w * v0.w;
            s1 += xv.x * v1.x + xv.y * v1.y + xv.z * v1.z + xv.w * v1.w;
        }
#pragma unroll
        for (int s = 16; s; s >>= 1) {
            s0 += __shfl_xor_sync(0xFFFFFFFFu, s0, s);
            s1 += __shfl_xor_sync(0xFFFFFFFFu, s1, s);
        }
        if (lid == 0) {
            g_xh[(size_t)t * KPAD + 8192 + 2 * w]     = __float2half_rn(s0);
            g_xh[(size_t)t * KPAD + 8192 + 2 * w + 1] = __float2half_rn(s1);
        }
    } else if (blk < T1_BLOCKS + XC_BLOCKS) {
        // ---- xconv ----
        int tid = (blk - T1_BLOCKS) * 256 + threadIdx.x;
        const int MAIN = TOKENS * IN_F / 8;  // 262144
        if (tid < MAIN) {
            int e = tid << 3;
            int t = e >> 13, i = e & 8191;
            float4 f0 = *(const float4*)(x + e);
            float4 f1 = *(const float4*)(x + e + 4);
            __half2 h0 = __floats2half2_rn(f0.x, f0.y);
            __half2 h1 = __floats2half2_rn(f0.z, f0.w);
            __half2 h2 = __floats2half2_rn(f1.x, f1.y);
            __half2 h3 = __floats2half2_rn(f1.z, f1.w);
            uint4 v;
            v.x = *(uint32_t*)&h0; v.y = *(uint32_t*)&h1;
            v.z = *(uint32_t*)&h2; v.w = *(uint32_t*)&h3;
            *(uint4*)(g_xh + (size_t)t * KPAD + i) = v;
        } else {
            int p = tid - MAIN;
            if (p < TOKENS * 6) {
                int t = p / 6, u = p % 6;
                uint4 z = {0u, 0u, 0u, 0u};
                *(uint4*)(g_xh + (size_t)t * KPAD + 8208 + u * 8) = z;
            }
        }
    } else {
        // ---- probe ----
        __shared__ int cnt[2];
        if (threadIdx.x < 2) cnt[threadIdx.x] = 0;
        __syncthreads();
        if (threadIdx.x < 128) {
            float f = __uint_as_float(((const uint32_t*)wn)[threadIdx.x]);
            if (f > 0.004f && f < 1.05f) atomicAdd(&cnt[0], 1);
        }
        {
            uint16_t h = ((const uint16_t*)wn)[threadIdx.x];
            if (h < 0x3C08u) atomicAdd(&cnt[1], 1);
        }
        __syncthreads();
        if (threadIdx.x == 0) {
            if (cnt[0] >= 100)      g_wn_mode = 0;
            else if (cnt[1] >= 128) g_wn_mode = 1;
            else                    g_wn_mode = 2;
        }
    }
}

// ---------------- GEMM: fused dequant, CTA 128x128, ldmatrix fragments -----
// grid (64, 2), 256 threads / 8 warps (warp grid 4M x 2N, warp tile 32x64).
// Fragment building: 24 ldmatrix.x4 per warp per iter (was 96 scalar LDS).
#define ROWP 72
#define TILE_B (128 * ROWP * 2)       // 18432 bytes
#define SM_A 0                        // 3 A buffers
#define SM_B (3 * TILE_B)             // 2 B buffers
#define SM_SEL (SM_B + 2 * TILE_B)    // PRMT selector table
#define GEMM_SMEM (SM_SEL + 1024)     // 93184

__device__ __forceinline__ void mma16816(float& c0, float& c1, float& c2, float& c3,
                                         uint32_t a0, uint32_t a1, uint32_t a2, uint32_t a3,
                                         uint32_t b0, uint32_t b1) {
    asm volatile("mma.sync.aligned.m16n8k16.row.col.f32.f16.f16.f32 "
                 "{%0,%1,%2,%3}, {%4,%5,%6,%7}, {%8,%9}, {%0,%1,%2,%3};"
                 : "+f"(c0), "+f"(c1), "+f"(c2), "+f"(c3)
                 : "r"(a0), "r"(a1), "r"(a2), "r"(a3), "r"(b0), "r"(b1));
}

__device__ __forceinline__ void ldsm4(uint32_t& r0, uint32_t& r1, uint32_t& r2, uint32_t& r3,
                                      uint32_t addr) {
    asm volatile("ldmatrix.sync.aligned.m8n8.x4.shared.b16 {%0,%1,%2,%3}, [%4];"
                 : "=r"(r0), "=r"(r1), "=r"(r2), "=r"(r3) : "r"(addr));
}

__device__ __forceinline__ float load_norm(const void* wn, int g, int mode) {
    if (mode == 0) return ((const float*)wn)[g];
    if (mode == 1) return __half2float(((const __half*)wn)[g]);
    return __bfloat162float(((const __nv_bfloat16*)wn)[g]);
}

__global__ void __launch_bounds__(256) qlora_gemm(const int* __restrict__ q2,
                                                  const void* __restrict__ wn,
                                                  const float* __restrict__ lb,
                                                  const float* __restrict__ bias,
                                                  float* __restrict__ out) {
    extern __shared__ char smem[];
    const uint32_t sb = smem_u32(smem);
    const int tid = threadIdx.x;
    const int wid = tid >> 5;
    const int lid = tid & 31;
    const int bx = blockIdx.x;       // N tile 0..63
    const int by = blockIdx.y;       // M tile 0..1
    const int wm = wid & 3;          // 4 M-warps x 32 rows
    const int wn2 = wid >> 2;        // 2 N-warps x 64 cols
    const int fr = lid >> 2;
    const int fc = (lid & 3) << 1;
    const int mode = g_wn_mode;

    uint32_t* selt = (uint32_t*)(smem + SM_SEL);
    {
        int b = tid;
        selt[b] = (uint32_t)((b & 3) | (((b >> 2) & 3) << 4) |
                             (((b >> 4) & 3) << 8) | (((b >> 6) & 3) << 12));
    }

    // ldmatrix lane-address offsets (bytes, relative to tile base)
    // A (m16k16 per mi): row = l&15 (+8-col group l>>4)
    uint32_t aFragOff[2];
#pragma unroll
    for (int mi = 0; mi < 2; mi++)
        aFragOff[mi] = ((uint32_t)(wm * 32 + mi * 16 + (lid & 15)) * ROWP
                        + (uint32_t)(lid >> 4) * 8) * 2;
    // B (n16k16 per ni2): row = ((l>>4)&1)*8 + (l&7); k-half (l>>3)&1
    uint32_t bFragOff[4];
#pragma unroll
    for (int ni2 = 0; ni2 < 4; ni2++)
        bFragOff[ni2] = ((uint32_t)(wn2 * 64 + ni2 * 16 + ((lid >> 4) & 1) * 8 + (lid & 7)) * ROWP
                         + (uint32_t)((lid >> 3) & 1) * 8) * 2;

    // B decode: 2 threads per row (128 rows), 8 int32 codes each
    const int brow = tid >> 1;
    const int hs = tid & 1;
    const int o = bx * 128 + brow;
    const int* crow = q2 + (size_t)o * 2048;

    const __half* Ag = g_xh + (size_t)(by * 128 + brow) * KPAD;
    const uint32_t a_off = (uint32_t)brow * (ROWP * 2) + (uint32_t)hs * 64;

    auto issueA = [&](int buf3, int kk) {
        uint32_t dst = sb + SM_A + buf3 * TILE_B + a_off;
        const char* src = (const char*)(Ag + kk + hs * 32);
#pragma unroll
        for (int u = 0; u < 4; u++)
            asm volatile("cp.async.cg.shared.global [%0], [%1], 16;"
                         :: "r"(dst + u * 16), "l"(src + u * 16) : "memory");
    };

    auto decodeSTS = [&](int j, uint4 C0, uint4 C1, float n) {
        uint32_t r[16];
        if (j < 128) {
            float n3 = n * 0.33333334f;
            __half h0 = __float2half_rn(-n),  h1 = __float2half_rn(-n3);
            __half h2 = __float2half_rn(n3),  h3 = __float2half_rn(n);
            uint32_t p01 = (uint32_t)__half_as_ushort(h0) | ((uint32_t)__half_as_ushort(h1) << 16);
            uint32_t p23 = (uint32_t)__half_as_ushort(h2) | ((uint32_t)__half_as_ushort(h3) << 16);
            uint32_t t_lo = __byte_perm(p01, p23, 0x6420);
            uint32_t t_hi = __byte_perm(p01, p23, 0x7531);
            uint32_t w[8] = {C0.x, C0.y, C0.z, C0.w, C1.x, C1.y, C1.z, C1.w};
#pragma unroll
            for (int i = 0; i < 8; i++) {
                uint32_t sel = selt[w[i] & 0xFF];
                uint32_t lo4 = __byte_perm(t_lo, 0u, sel);
                uint32_t hi4 = __byte_perm(t_hi, 0u, sel);
                r[2 * i]     = __byte_perm(lo4, hi4, 0x5140);
                r[2 * i + 1] = __byte_perm(lo4, hi4, 0x7362);
            }
        } else {
#pragma unroll
            for (int i = 0; i < 16; i++) r[i] = 0u;
            if (hs == 0) {
                r[0] = C0.x; r[1] = C0.y; r[2] = C0.z; r[3] = C0.w;
                r[4] = C1.x; r[5] = C1.y; r[6] = C1.z; r[7] = C1.w;
            }
        }
        char* dst = smem + SM_B + (j & 1) * TILE_B + brow * (ROWP * 2) + hs * 64;
        *(uint4*)(dst)      = make_uint4(r[0], r[1], r[2], r[3]);
        *(uint4*)(dst + 16) = make_uint4(r[4], r[5], r[6], r[7]);
        *(uint4*)(dst + 32) = make_uint4(r[8], r[9], r[10], r[11]);
        *(uint4*)(dst + 48) = make_uint4(r[12], r[13], r[14], r[15]);
    };

    auto loadCodes = [&](int j, uint4& C0, uint4& C1, float& n) {
        if (j < 128) {
            const uint4* p = (const uint4*)(crow + j * 16 + hs * 8);
            C0 = __ldg(p);
            C1 = __ldg(p + 1);
            n = load_norm(wn, o * 64 + (j >> 1), mode);
        } else if (hs == 0) {
            const float4* s = (const float4*)(lb + (size_t)o * 16);
            float4 f0 = __ldg(s), f1 = __ldg(s + 1), f2 = __ldg(s + 2), f3 = __ldg(s + 3);
            __half2 a0 = __floats2half2_rn(f0.x, f0.y), a1 = __floats2half2_rn(f0.z, f0.w);
            __half2 a2 = __floats2half2_rn(f1.x, f1.y), a3 = __floats2half2_rn(f1.z, f1.w);
            __half2 a4 = __floats2half2_rn(f2.x, f2.y), a5 = __floats2half2_rn(f2.z, f2.w);
            __half2 a6 = __floats2half2_rn(f3.x, f3.y), a7 = __floats2half2_rn(f3.z, f3.w);
            C0 = make_uint4(*(uint32_t*)&a0, *(uint32_t*)&a1, *(uint32_t*)&a2, *(uint32_t*)&a3);
            C1 = make_uint4(*(uint32_t*)&a4, *(uint32_t*)&a5, *(uint32_t*)&a6, *(uint32_t*)&a7);
        }
    };

    float acc[2][8][4];
#pragma unroll
    for (int mi = 0; mi < 2; mi++)
#pragma unroll
        for (int ni = 0; ni < 8; ni++)
#pragma unroll
            for (int r = 0; r < 4; r++) acc[mi][ni][r] = 0.f;

    uint4 C0 = {0, 0, 0, 0}, C1 = {0, 0, 0, 0};
    float cn = 0.f;
    loadCodes(0, C0, C1, cn);
    __syncthreads();
    decodeSTS(0, C0, C1, cn);
    issueA(0, 0);  asm volatile("cp.async.commit_group;" ::: "memory");
    issueA(1, 64); asm volatile("cp.async.commit_group;" ::: "memory");
    loadCodes(1, C0, C1, cn);
    __syncthreads();

    int abuf = 0;
    for (int it = 0; it < NITER; it++) {
        asm volatile("cp.async.wait_group 1;" ::: "memory");
        __syncthreads();

        const uint32_t aBase = sb + SM_A + abuf * TILE_B;
        const uint32_t bBase = sb + SM_B + (it & 1) * TILE_B;

#pragma unroll
        for (int ks = 0; ks < 2; ks++) {
            const uint32_t ksb = (uint32_t)ks * 32;
            uint32_t a[2][4];
            ldsm4(a[0][0], a[0][1], a[0][2], a[0][3], aBase + aFragOff[0] + ksb);
            ldsm4(a[1][0], a[1][1], a[1][2], a[1][3], aBase + aFragOff[1] + ksb);
#pragma unroll
            for (int ni2 = 0; ni2 < 4; ni2++) {
                uint32_t b0, b1, b2, b3;
                ldsm4(b0, b1, b2, b3, bBase + bFragOff[ni2] + ksb);
#pragma unroll
                for (int mi = 0; mi < 2; mi++) {
                    mma16816(acc[mi][2 * ni2][0], acc[mi][2 * ni2][1],
                             acc[mi][2 * ni2][2], acc[mi][2 * ni2][3],
                             a[mi][0], a[mi][1], a[mi][2], a[mi][3], b0, b1);
                    mma16816(acc[mi][2 * ni2 + 1][0], acc[mi][2 * ni2 + 1][1],
                             acc[mi][2 * ni2 + 1][2], acc[mi][2 * ni2 + 1][3],
                             a[mi][0], a[mi][1], a[mi][2], a[mi][3], b2, b3);
                }
            }
        }

        if (it <= 127) decodeSTS(it + 1, C0, C1, cn);
        if (it + 2 <= 128) loadCodes(it + 2, C0, C1, cn);
        if (it + 2 < NITER) {
            int nb = abuf + 2; if (nb >= 3) nb -= 3;
            issueA(nb, (it + 2) * 64);
        }
        asm volatile("cp.async.commit_group;" ::: "memory");

#pragma unroll
        for (int ks = 2; ks < 4; ks++) {
            const uint32_t ksb = (uint32_t)ks * 32;
            uint32_t a[2][4];
            ldsm4(a[0][0], a[0][1], a[0][2], a[0][3], aBase + aFragOff[0] + ksb);
            ldsm4(a[1][0], a[1][1], a[1][2], a[1][3], aBase + aFragOff[1] + ksb);
#pragma unroll
            for (int ni2 = 0; ni2 < 4; ni2++) {
                uint32_t b0, b1, b2, b3;
                ldsm4(b0, b1, b2, b3, bBase + bFragOff[ni2] + ksb);
#pragma unroll
                for (int mi = 0; mi < 2; mi++) {
                    mma16816(acc[mi][2 * ni2][0], acc[mi][2 * ni2][1],
                             acc[mi][2 * ni2][2], acc[mi][2 * ni2][3],
                             a[mi][0], a[mi][1], a[mi][2], a[mi][3], b0, b1);
                    mma16816(acc[mi][2 * ni2 + 1][0], acc[mi][2 * ni2 + 1][1],
                             acc[mi][2 * ni2 + 1][2], acc[mi][2 * ni2 + 1][3],
                             a[mi][0], a[mi][1], a[mi][2], a[mi][3], b2, b3);
                }
            }
        }

        abuf++; if (abuf == 3) abuf = 0;
    }
    asm volatile("cp.async.wait_group 0;" ::: "memory");

    const int m0 = by * 128 + wm * 32 + fr;
    const int n00 = bx * 128 + wn2 * 64 + fc;
#pragma unroll
    for (int mi = 0; mi < 2; mi++) {
#pragma unroll
        for (int ni = 0; ni < 8; ni++) {
            int n = n00 + ni * 8;
            float b0 = __ldg(bias + n), b1 = __ldg(bias + n + 1);
            int mA = m0 + mi * 16;
            float2 v0 = {acc[mi][ni][0] + b0, acc[mi][ni][1] + b1};
            float2 v1 = {acc[mi][ni][2] + b0, acc[mi][ni][3] + b1};
            *(float2*)(out + (size_t)mA * OUT_F + n) = v0;
            *(float2*)(out + (size_t)(mA + 8) * OUT_F + n) = v1;
        }
    }
}

// ---------------- launch ----------------
extern "C" void kernel_launch(void* const* d_in, const int* in_sizes, int n_in,
                              void* d_out, int out_size) {
    int ix = -1, iq = -1, iwn = -1, ib = -1, ila = -1, ilb = -1;
    for (int i = 0; i < n_in; i++) {
        int s = in_sizes[i];
        if (s == TOKENS * IN_F)            ix = i;
        else if (s == OUT_F * IN_F / 4)    iq = i;
        else if (s == OUT_F * IN_F / 128)  iwn = i;
        else if (s == OUT_F)               ib = i;
        else if (s == 16 * IN_F)           { if (ila < 0) ila = i; else ilb = i; }
    }
    const float* x    = (const float*)d_in[ix];
    const int*   q2   = (const int*)d_in[iq];
    const void*  wn   = (const void*)d_in[iwn];
    const float* bias = (const float*)d_in[ib];
    const float* la   = (const float*)d_in[ila];
    const float* lb   = (const float*)d_in[ilb];
    float* out = (float*)d_out;

    qlora_prep<<<PREP_BLOCKS, 256>>>(x, la, wn);

    cudaFuncSetAttribute(qlora_gemm, cudaFuncAttributeMaxDynamicSharedMemorySize, GEMM_SMEM);
    qlora_gemm<<<dim3(64, 2), 256, GEMM_SMEM>>>(q2, wn, lb, bias, out);
}

// round 16
// speedup vs baseline: 2.3468x; 1.1455x over previous
#include <cuda_runtime.h>
#include <cuda_fp16.h>
#include <cuda_bf16.h>
#include <cstdint>

#define OUT_F 8192
#define IN_F  8192
#define TOKENS 256
#define KPAD  8256          // 8192 + 16 lora cols + 48 zero pad
#define NITER 129           // KPAD / 64

// Scratch (device globals — no cudaMalloc allowed)
__device__ __half g_xh[(size_t)TOKENS * KPAD];  // x fp16 | t1 fp16 | zeros
__device__ int g_wn_mode;                       // 0=f32, 1=f16, 2=bf16

__device__ __forceinline__ uint32_t smem_u32(const void* p) {
    uint32_t a;
    asm("{ .reg .u64 t; cvta.to.shared.u64 t, %1; cvt.u32.u64 %0, t; }" : "=r"(a) : "l"(p));
    return a;
}

// ---------------- prep: t1 (long poles first) + xconv + probe --------------
#define T1_BLOCKS 256
#define XC_BLOCKS 1030
#define PREP_BLOCKS (T1_BLOCKS + XC_BLOCKS + 1)

__global__ void __launch_bounds__(256) qlora_prep(const float* __restrict__ x,
                                                  const float* __restrict__ la,
                                                  const void* __restrict__ wn) {
    const int blk = blockIdx.x;
    if (blk < T1_BLOCKS) {
        // ---- t1: token = block; warp w handles lora rows 2w, 2w+1 ----
        const int t = blk;
        const int w = threadIdx.x >> 5;
        const int lid = threadIdx.x & 31;
        const float* xrow = x + (size_t)t * IN_F;
        const float* a0 = la + (size_t)(2 * w) * IN_F;
        const float* a1 = la + (size_t)(2 * w + 1) * IN_F;
        float s0 = 0.f, s1 = 0.f;
#pragma unroll 2
        for (int i = 0; i < 64; i++) {
            int k = i * 128 + lid * 4;
            float4 xv = *(const float4*)(xrow + k);
            float4 v0 = __ldg((const float4*)(a0 + k));
            float4 v1 = __ldg((const float4*)(a1 + k));
            s0 += xv.x * v0.x + xv.y * v0.y + xv.z * v0.z + xv.w * v0.w;
            s1 += xv.x * v1.x + xv.y * v1.y + xv.z * v1.z + xv.w * v1.w;
        }
#pragma unroll
        for (int s = 16; s; s >>= 1) {
            s0 += __shfl_xor_sync(0xFFFFFFFFu, s0, s);
            s1 += __shfl_xor_sync(0xFFFFFFFFu, s1, s);
        }
        if (lid == 0) {
            g_xh[(size_t)t * KPAD + 8192 + 2 * w]     = __float2half_rn(s0);
            g_xh[(size_t)t * KPAD + 8192 + 2 * w + 1] = __float2half_rn(s1);
        }
    } else if (blk < T1_BLOCKS + XC_BLOCKS) {
        // ---- xconv ----
        int tid = (blk - T1_BLOCKS) * 256 + threadIdx.x;
        const int MAIN = TOKENS * IN_F / 8;  // 262144
        if (tid < MAIN) {
            int e = tid << 3;
            int t = e >> 13, i = e & 8191;
            float4 f0 = *(const float4*)(x + e);
            float4 f1 = *(const float4*)(x + e + 4);
            __half2 h0 = __floats2half2_rn(f0.x, f0.y);
            __half2 h1 = __floats2half2_rn(f0.z, f0.w);
            __half2 h2 = __floats2half2_rn(f1.x, f1.y);
            __half2 h3 = __floats2half2_rn(f1.z, f1.w);
            uint4 v;
            v.x = *(uint32_t*)&h0; v.y = *(uint32_t*)&h1;
            v.z = *(uint32_t*)&h2; v.w = *(uint32_t*)&h3;
            *(uint4*)(g_xh + (size_t)t * KPAD + i) = v;
        } else {
            int p = tid - MAIN;
            if (p < TOKENS * 6) {
                int t = p / 6, u = p % 6;
                uint4 z = {0u, 0u, 0u, 0u};
                *(uint4*)(g_xh + (size_t)t * KPAD + 8208 + u * 8) = z;
            }
        }
    } else {
        // ---- probe ----
        __shared__ int cnt[2];
        if (threadIdx.x < 2) cnt[threadIdx.x] = 0;
        __syncthreads();
        if (threadIdx.x < 128) {
            float f = __uint_as_float(((const uint32_t*)wn)[threadIdx.x]);
            if (f > 0.004f && f < 1.05f) atomicAdd(&cnt[0], 1);
        }
        {
            uint16_t h = ((const uint16_t*)wn)[threadIdx.x];
            if (h < 0x3C08u) atomicAdd(&cnt[1], 1);
        }
        __syncthreads();
        if (threadIdx.x == 0) {
            if (cnt[0] >= 100)      g_wn_mode = 0;
            else if (cnt[1] >= 128) g_wn_mode = 1;
            else                    g_wn_mode = 2;
        }
    }
}

// ---------------- GEMM: fused dequant, CTA 128x128, 512 thr, ldmatrix ------
// grid (64, 2), 16 warps: warp grid 4(M) x 4(N), warp tile 32x32, acc 32 regs.
// Per warp per ks: 2 A ldsm.x4 + 2 B ldsm.x4 + 8 mma. 4 warps/SMSP hide
// HMMA latency (R15 evidence: tensor 34% @ 2 warps/SMSP = latency-bound).
// Decode volume per CTA unchanged (each thread 4 int32, R13-proven mapping).
#define ROWP 72
#define TILE_B (128 * ROWP * 2)       // 18432 bytes
#define SM_A 0                        // 3 A buffers
#define SM_B (3 * TILE_B)             // 2 B buffers
#define SM_SEL (SM_B + 2 * TILE_B)    // PRMT selector table
#define GEMM_SMEM (SM_SEL + 1024)     // 93184

__device__ __forceinline__ void mma16816(float& c0, float& c1, float& c2, float& c3,
                                         uint32_t a0, uint32_t a1, uint32_t a2, uint32_t a3,
                                         uint32_t b0, uint32_t b1) {
    asm volatile("mma.sync.aligned.m16n8k16.row.col.f32.f16.f16.f32 "
                 "{%0,%1,%2,%3}, {%4,%5,%6,%7}, {%8,%9}, {%0,%1,%2,%3};"
                 : "+f"(c0), "+f"(c1), "+f"(c2), "+f"(c3)
                 : "r"(a0), "r"(a1), "r"(a2), "r"(a3), "r"(b0), "r"(b1));
}

__device__ __forceinline__ void ldsm4(uint32_t& r0, uint32_t& r1, uint32_t& r2, uint32_t& r3,
                                      uint32_t addr) {
    asm volatile("ldmatrix.sync.aligned.m8n8.x4.shared.b16 {%0,%1,%2,%3}, [%4];"
                 : "=r"(r0), "=r"(r1), "=r"(r2), "=r"(r3) : "r"(addr));
}

__device__ __forceinline__ float load_norm(const void* wn, int g, int mode) {
    if (mode == 0) return ((const float*)wn)[g];
    if (mode == 1) return __half2float(((const __half*)wn)[g]);
    return __bfloat162float(((const __nv_bfloat16*)wn)[g]);
}

__global__ void __launch_bounds__(512, 1) qlora_gemm(const int* __restrict__ q2,
                                                     const void* __restrict__ wn,
                                                     const float* __restrict__ lb,
                                                     const float* __restrict__ bias,
                                                     float* __restrict__ out) {
    extern __shared__ char smem[];
    const uint32_t sb = smem_u32(smem);
    const int tid = threadIdx.x;
    const int wid = tid >> 5;
    const int lid = tid & 31;
    const int bx = blockIdx.x;       // N tile 0..63
    const int by = blockIdx.y;       // M tile 0..1
    const int wm = wid & 3;          // 4 M-warps x 32 rows
    const int wn2 = wid >> 2;        // 4 N-warps x 32 cols
    const int fr = lid >> 2;
    const int fc = (lid & 3) << 1;
    const int mode = g_wn_mode;

    uint32_t* selt = (uint32_t*)(smem + SM_SEL);
    if (tid < 256) {
        int b = tid;
        selt[b] = (uint32_t)((b & 3) | (((b >> 2) & 3) << 4) |
                             (((b >> 4) & 3) << 8) | (((b >> 6) & 3) << 12));
    }

    // ldmatrix lane-address offsets (bytes, relative to tile base)
    uint32_t aFragOff[2];
#pragma unroll
    for (int mi = 0; mi < 2; mi++)
        aFragOff[mi] = ((uint32_t)(wm * 32 + mi * 16 + (lid & 15)) * ROWP
                        + (uint32_t)(lid >> 4) * 8) * 2;
    uint32_t bFragOff[2];
#pragma unroll
    for (int ni2 = 0; ni2 < 2; ni2++)
        bFragOff[ni2] = ((uint32_t)(wn2 * 32 + ni2 * 16 + ((lid >> 4) & 1) * 8 + (lid & 7)) * ROWP
                         + (uint32_t)((lid >> 3) & 1) * 8) * 2;

    // B decode: 4 threads per row (128 rows); each thread 4 int32 = 16 codes
    const int brow = tid >> 2;
    const int hs = tid & 3;
    const int o = bx * 128 + brow;
    const int* crow = q2 + (size_t)o * 2048;

    // A producer: 128 rows, 4 threads/row, 32B each
    const __half* Ag = g_xh + (size_t)(by * 128 + brow) * KPAD;
    const uint32_t a_off = (uint32_t)brow * (ROWP * 2) + (uint32_t)hs * 32;

    auto issueA = [&](int buf3, int kk) {
        uint32_t dst = sb + SM_A + buf3 * TILE_B + a_off;
        const char* src = (const char*)(Ag + kk + hs * 16);
        asm volatile("cp.async.cg.shared.global [%0], [%1], 16;"
                     :: "r"(dst), "l"(src) : "memory");
        asm volatile("cp.async.cg.shared.global [%0], [%1], 16;"
                     :: "r"(dst + 16), "l"(src + 16) : "memory");
    };

    // decode 4 int32 codes (C0) with norm n -> 8 u32 halves -> STS (32B)
    auto decodeSTS = [&](int j, uint4 C0, uint4 C1, float n) {
        uint32_t r[8];
        if (j < 128) {
            float n3 = n * 0.33333334f;
            __half h0 = __float2half_rn(-n),  h1 = __float2half_rn(-n3);
            __half h2 = __float2half_rn(n3),  h3 = __float2half_rn(n);
            uint32_t p01 = (uint32_t)__half_as_ushort(h0) | ((uint32_t)__half_as_ushort(h1) << 16);
            uint32_t p23 = (uint32_t)__half_as_ushort(h2) | ((uint32_t)__half_as_ushort(h3) << 16);
            uint32_t t_lo = __byte_perm(p01, p23, 0x6420);
            uint32_t t_hi = __byte_perm(p01, p23, 0x7531);
            uint32_t w[4] = {C0.x, C0.y, C0.z, C0.w};
#pragma unroll
            for (int i = 0; i < 4; i++) {
                uint32_t sel = selt[w[i] & 0xFF];
                uint32_t lo4 = __byte_perm(t_lo, 0u, sel);
                uint32_t hi4 = __byte_perm(t_hi, 0u, sel);
                r[2 * i]     = __byte_perm(lo4, hi4, 0x5140);
                r[2 * i + 1] = __byte_perm(lo4, hi4, 0x7362);
            }
        } else {
            // j == 128: cols 0-15 = lora_b (hs==0 covers cols 0-15), rest 0
#pragma unroll
            for (int i = 0; i < 8; i++) r[i] = 0u;
            if (hs == 0) {
                r[0] = C0.x; r[1] = C0.y; r[2] = C0.z; r[3] = C0.w;
                r[4] = C1.x; r[5] = C1.y; r[6] = C1.z; r[7] = C1.w;
            }
        }
        char* dst = smem + SM_B + (j & 1) * TILE_B + brow * (ROWP * 2) + hs * 32;
        *(uint4*)(dst)      = make_uint4(r[0], r[1], r[2], r[3]);
        *(uint4*)(dst + 16) = make_uint4(r[4], r[5], r[6], r[7]);
    };

    auto loadCodes = [&](int j, uint4& C0, uint4& C1, float& n) {
        if (j < 128) {
            C0 = __ldg((const uint4*)(crow + j * 16 + hs * 4));
            n = load_norm(wn, o * 64 + (j >> 1), mode);
        } else if (hs == 0) {
            const float4* s = (const float4*)(lb + (size_t)o * 16);
            float4 f0 = __ldg(s), f1 = __ldg(s + 1), f2 = __ldg(s + 2), f3 = __ldg(s + 3);
            __half2 a0 = __floats2half2_rn(f0.x, f0.y), a1 = __floats2half2_rn(f0.z, f0.w);
            __half2 a2 = __floats2half2_rn(f1.x, f1.y), a3 = __floats2half2_rn(f1.z, f1.w);
            __half2 a4 = __floats2half2_rn(f2.x, f2.y), a5 = __floats2half2_rn(f2.z, f2.w);
            __half2 a6 = __floats2half2_rn(f3.x, f3.y), a7 = __floats2half2_rn(f3.z, f3.w);
            C0 = make_uint4(*(uint32_t*)&a0, *(uint32_t*)&a1, *(uint32_t*)&a2, *(uint32_t*)&a3);
            C1 = make_uint4(*(uint32_t*)&a4, *(uint32_t*)&a5, *(uint32_t*)&a6, *(uint32_t*)&a7);
        }
    };

    float acc[2][4][4];
#pragma unroll
    for (int mi = 0; mi < 2; mi++)
#pragma unroll
        for (int ni = 0; ni < 4; ni++)
#pragma unroll
            for (int r = 0; r < 4; r++) acc[mi][ni][r] = 0.f;

    uint4 C0 = {0, 0, 0, 0}, C1 = {0, 0, 0, 0};
    float cn = 0.f;
    loadCodes(0, C0, C1, cn);
    __syncthreads();
    decodeSTS(0, C0, C1, cn);
    issueA(0, 0);  asm volatile("cp.async.commit_group;" ::: "memory");
    issueA(1, 64); asm volatile("cp.async.commit_group;" ::: "memory");
    loadCodes(1, C0, C1, cn);
    __syncthreads();

    int abuf = 0;
    for (int it = 0; it < NITER; it++) {
        asm volatile("cp.async.wait_group 1;" ::: "memory");
        __syncthreads();

        const uint32_t aBase = sb + SM_A + abuf * TILE_B;
        const uint32_t bBase = sb + SM_B + (it & 1) * TILE_B;

#pragma unroll
        for (int ks = 0; ks < 2; ks++) {
            const uint32_t ksb = (uint32_t)ks * 32;
            uint32_t a[2][4];
            ldsm4(a[0][0], a[0][1], a[0][2], a[0][3], aBase + aFragOff[0] + ksb);
            ldsm4(a[1][0], a[1][1], a[1][2], a[1][3], aBase + aFragOff[1] + ksb);
#pragma unroll
            for (int ni2 = 0; ni2 < 2; ni2++) {
                uint32_t b0, b1, b2, b3;
                ldsm4(b0, b1, b2, b3, bBase + bFragOff[ni2] + ksb);
#pragma unroll
                for (int mi = 0; mi < 2; mi++) {
                    mma16816(acc[mi][2 * ni2][0], acc[mi][2 * ni2][1],
                             acc[mi][2 * ni2][2], acc[mi][2 * ni2][3],
                             a[mi][0], a[mi][1], a[mi][2], a[mi][3], b0, b1);
                    mma16816(acc[mi][2 * ni2 + 1][0], acc[mi][2 * ni2 + 1][1],
                             acc[mi][2 * ni2 + 1][2], acc[mi][2 * ni2 + 1][3],
                             a[mi][0], a[mi][1], a[mi][2], a[mi][3], b2, b3);
                }
            }
        }

        if (it <= 127) decodeSTS(it + 1, C0, C1, cn);
        if (it + 2 <= 128) loadCodes(it + 2, C0, C1, cn);
        if (it + 2 < NITER) {
            int nb = abuf + 2; if (nb >= 3) nb -= 3;
            issueA(nb, (it + 2) * 64);
        }
        asm volatile("cp.async.commit_group;" ::: "memory");

#pragma unroll
        for (int ks = 2; ks < 4; ks++) {
            const uint32_t ksb = (uint32_t)ks * 32;
            uint32_t a[2][4];
            ldsm4(a[0][0], a[0][1], a[0][2], a[0][3], aBase + aFragOff[0] + ksb);
            ldsm4(a[1][0], a[1][1], a[1][2], a[1][3], aBase + aFragOff[1] + ksb);
#pragma unroll
            for (int ni2 = 0; ni2 < 2; ni2++) {
                uint32_t b0, b1, b2, b3;
                ldsm4(b0, b1, b2, b3, bBase + bFragOff[ni2] + ksb);
#pragma unroll
                for (int mi = 0; mi < 2; mi++) {
                    mma16816(acc[mi][2 * ni2][0], acc[mi][2 * ni2][1],
                             acc[mi][2 * ni2][2], acc[mi][2 * ni2][3],
                             a[mi][0], a[mi][1], a[mi][2], a[mi][3], b0, b1);
                    mma16816(acc[mi][2 * ni2 + 1][0], acc[mi][2 * ni2 + 1][1],
                             acc[mi][2 * ni2 + 1][2], acc[mi][2 * ni2 + 1][3],
                             a[mi][0], a[mi][1], a[mi][2], a[mi][3], b2, b3);
                }
            }
        }

        abuf++; if (abuf == 3) abuf = 0;
    }
    asm volatile("cp.async.wait_group 0;" ::: "memory");

    const int m0 = by * 128 + wm * 32 + fr;
    const int n00 = bx * 128 + wn2 * 32 + fc;
#pragma unroll
    for (int mi = 0; mi < 2; mi++) {
#pragma unroll
        for (int ni = 0; ni < 4; ni++) {
            int n = n00 + ni * 8;
            float b0 = __ldg(bias + n), b1 = __ldg(bias + n + 1);
            int mA = m0 + mi * 16;
            float2 v0 = {acc[mi][ni][0] + b0, acc[mi][ni][1] + b1};
            float2 v1 = {acc[mi][ni][2] + b0, acc[mi][ni][3] + b1};
            *(float2*)(out + (size_t)mA * OUT_F + n) = v0;
            *(float2*)(out + (size_t)(mA + 8) * OUT_F + n) = v1;
        }
    }
}

// ---------------- launch ----------------
extern "C" void kernel_launch(void* const* d_in, const int* in_sizes, int n_in,
                              void* d_out, int out_size) {
    int ix = -1, iq = -1, iwn = -1, ib = -1, ila = -1, ilb = -1;
    for (int i = 0; i < n_in; i++) {
        int s = in_sizes[i];
        if (s == TOKENS * IN_F)            ix = i;
        else if (s == OUT_F * IN_F / 4)    iq = i;
        else if (s == OUT_F * IN_F / 128)  iwn = i;
        else if (s == OUT_F)               ib = i;
        else if (s == 16 * IN_F)           { if (ila < 0) ila = i; else ilb = i; }
    }
    const float* x    = (const float*)d_in[ix];
    const int*   q2   = (const int*)d_in[iq];
    const void*  wn   = (const void*)d_in[iwn];
    const float* bias = (const float*)d_in[ib];
    const float* la   = (const float*)d_in[ila];
    const float* lb   = (const float*)d_in[ilb];
    float* out = (float*)d_out;

    qlora_prep<<<PREP_BLOCKS, 256>>>(x, la, wn);

    cudaFuncSetAttribute(qlora_gemm, cudaFuncAttributeMaxDynamicSharedMemorySize, GEMM_SMEM);
    qlora_gemm<<<dim3(64, 2), 512, GEMM_SMEM>>>(q2, wn, lb, bias, out);
}

// round 17
// speedup vs baseline: 2.3736x; 1.0114x over previous
#include <cuda_runtime.h>
#include <cuda_fp16.h>
#include <cuda_bf16.h>
#include <cstdint>

#define OUT_F 8192
#define IN_F  8192
#define TOKENS 256
#define KPAD  8256          // 8192 + 16 lora cols + 48 zero pad
#define NITER 129           // KPAD / 64

// Scratch (device globals — no cudaMalloc allowed)
__device__ __half g_xh[(size_t)TOKENS * KPAD];  // x fp16 | t1 fp16 | zeros
__device__ int g_wn_mode;                       // 0=f32, 1=f16, 2=bf16

__device__ __forceinline__ uint32_t smem_u32(const void* p) {
    uint32_t a;
    asm("{ .reg .u64 t; cvta.to.shared.u64 t, %1; cvt.u32.u64 %0, t; }" : "=r"(a) : "l"(p));
    return a;
}

// ---------------- prep: t1 (long poles first) + xconv + probe --------------
#define T1_BLOCKS 256
#define XC_BLOCKS 1030
#define PREP_BLOCKS (T1_BLOCKS + XC_BLOCKS + 1)

__global__ void __launch_bounds__(256) qlora_prep(const float* __restrict__ x,
                                                  const float* __restrict__ la,
                                                  const void* __restrict__ wn) {
    const int blk = blockIdx.x;
    if (blk < T1_BLOCKS) {
        const int t = blk;
        const int w = threadIdx.x >> 5;
        const int lid = threadIdx.x & 31;
        const float* xrow = x + (size_t)t * IN_F;
        const float* a0 = la + (size_t)(2 * w) * IN_F;
        const float* a1 = la + (size_t)(2 * w + 1) * IN_F;
        float s0 = 0.f, s1 = 0.f;
#pragma unroll 2
        for (int i = 0; i < 64; i++) {
            int k = i * 128 + lid * 4;
            float4 xv = *(const float4*)(xrow + k);
            float4 v0 = __ldg((const float4*)(a0 + k));
            float4 v1 = __ldg((const float4*)(a1 + k));
            s0 += xv.x * v0.x + xv.y * v0.y + xv.z * v0.z + xv.w * v0.w;
            s1 += xv.x * v1.x + xv.y * v1.y + xv.z * v1.z + xv.w * v1.w;
        }
#pragma unroll
        for (int s = 16; s; s >>= 1) {
            s0 += __shfl_xor_sync(0xFFFFFFFFu, s0, s);
            s1 += __shfl_xor_sync(0xFFFFFFFFu, s1, s);
        }
        if (lid == 0) {
            g_xh[(size_t)t * KPAD + 8192 + 2 * w]     = __float2half_rn(s0);
            g_xh[(size_t)t * KPAD + 8192 + 2 * w + 1] = __float2half_rn(s1);
        }
    } else if (blk < T1_BLOCKS + XC_BLOCKS) {
        int tid = (blk - T1_BLOCKS) * 256 + threadIdx.x;
        const int MAIN = TOKENS * IN_F / 8;  // 262144
        if (tid < MAIN) {
            int e = tid << 3;
            int t = e >> 13, i = e & 8191;
            float4 f0 = *(const float4*)(x + e);
            float4 f1 = *(const float4*)(x + e + 4);
            __half2 h0 = __floats2half2_rn(f0.x, f0.y);
            __half2 h1 = __floats2half2_rn(f0.z, f0.w);
            __half2 h2 = __floats2half2_rn(f1.x, f1.y);
            __half2 h3 = __floats2half2_rn(f1.z, f1.w);
            uint4 v;
            v.x = *(uint32_t*)&h0; v.y = *(uint32_t*)&h1;
            v.z = *(uint32_t*)&h2; v.w = *(uint32_t*)&h3;
            *(uint4*)(g_xh + (size_t)t * KPAD + i) = v;
        } else {
            int p = tid - MAIN;
            if (p < TOKENS * 6) {
                int t = p / 6, u = p % 6;
                uint4 z = {0u, 0u, 0u, 0u};
                *(uint4*)(g_xh + (size_t)t * KPAD + 8208 + u * 8) = z;
            }
        }
    } else {
        __shared__ int cnt[2];
        if (threadIdx.x < 2) cnt[threadIdx.x] = 0;
        __syncthreads();
        if (threadIdx.x < 128) {
            float f = __uint_as_float(((const uint32_t*)wn)[threadIdx.x]);
            if (f > 0.004f && f < 1.05f) atomicAdd(&cnt[0], 1);
        }
        {
            uint16_t h = ((const uint16_t*)wn)[threadIdx.x];
            if (h < 0x3C08u) atomicAdd(&cnt[1], 1);
        }
        __syncthreads();
        if (threadIdx.x == 0) {
            if (cnt[0] >= 100)      g_wn_mode = 0;
            else if (cnt[1] >= 128) g_wn_mode = 1;
            else                    g_wn_mode = 2;
        }
    }
}

// ---------------- GEMM: warp-specialized, CTA 128x128, 512 threads ---------
// Warps 0-7: CONSUMERS (warp grid 4M x 2N, warp tile 32x64, pure ldsm+mma).
// Warps 8-15: PRODUCERS (B decode 2thr/row 8xint32, A cp.async 2thr/row).
// One __syncthreads per iter; producers fill B(it+1)&1 / A(it+2)%3 while
// consumers read B(it)&1 / A(it)%3 — disjoint buffers.
#define ROWP 72
#define TILE_B (128 * ROWP * 2)       // 18432 bytes
#define SM_A 0                        // 3 A buffers
#define SM_B (3 * TILE_B)             // 2 B buffers
#define SM_SEL (SM_B + 2 * TILE_B)    // PRMT selector table
#define GEMM_SMEM (SM_SEL + 1024)     // 93184

__device__ __forceinline__ void mma16816(float& c0, float& c1, float& c2, float& c3,
                                         uint32_t a0, uint32_t a1, uint32_t a2, uint32_t a3,
                                         uint32_t b0, uint32_t b1) {
    asm volatile("mma.sync.aligned.m16n8k16.row.col.f32.f16.f16.f32 "
                 "{%0,%1,%2,%3}, {%4,%5,%6,%7}, {%8,%9}, {%0,%1,%2,%3};"
                 : "+f"(c0), "+f"(c1), "+f"(c2), "+f"(c3)
                 : "r"(a0), "r"(a1), "r"(a2), "r"(a3), "r"(b0), "r"(b1));
}

__device__ __forceinline__ void ldsm4(uint32_t& r0, uint32_t& r1, uint32_t& r2, uint32_t& r3,
                                      uint32_t addr) {
    asm volatile("ldmatrix.sync.aligned.m8n8.x4.shared.b16 {%0,%1,%2,%3}, [%4];"
                 : "=r"(r0), "=r"(r1), "=r"(r2), "=r"(r3) : "r"(addr));
}

__device__ __forceinline__ float load_norm(const void* wn, int g, int mode) {
    if (mode == 0) return ((const float*)wn)[g];
    if (mode == 1) return __half2float(((const __half*)wn)[g]);
    return __bfloat162float(((const __nv_bfloat16*)wn)[g]);
}

__global__ void __launch_bounds__(512, 1) qlora_gemm(const int* __restrict__ q2,
                                                     const void* __restrict__ wn,
                                                     const float* __restrict__ lb,
                                                     const float* __restrict__ bias,
                                                     float* __restrict__ out) {
    extern __shared__ char smem[];
    const uint32_t sb = smem_u32(smem);
    const int tid = threadIdx.x;
    const int wid = tid >> 5;
    const int lid = tid & 31;
    const int bx = blockIdx.x;       // N tile 0..63
    const int by = blockIdx.y;       // M tile 0..1
    const bool consumer = (wid < 8);
    const int mode = g_wn_mode;

    uint32_t* selt = (uint32_t*)(smem + SM_SEL);
    if (tid < 256) {
        int b = tid;
        selt[b] = (uint32_t)((b & 3) | (((b >> 2) & 3) << 4) |
                             (((b >> 4) & 3) << 8) | (((b >> 6) & 3) << 12));
    }

    // ---- consumer state (warps 0-7): warp grid 4M x 2N, tile 32x64 ----
    const int wm = wid & 3;
    const int wn2 = wid >> 2;        // 0..1 for consumers
    const int fr = lid >> 2;
    const int fc = (lid & 3) << 1;
    uint32_t aFragOff[2], bFragOff[4];
#pragma unroll
    for (int mi = 0; mi < 2; mi++)
        aFragOff[mi] = ((uint32_t)(wm * 32 + mi * 16 + (lid & 15)) * ROWP
                        + (uint32_t)(lid >> 4) * 8) * 2;
#pragma unroll
    for (int ni2 = 0; ni2 < 4; ni2++)
        bFragOff[ni2] = ((uint32_t)(wn2 * 64 + ni2 * 16 + ((lid >> 4) & 1) * 8 + (lid & 7)) * ROWP
                         + (uint32_t)((lid >> 3) & 1) * 8) * 2;

    // ---- producer state (warps 8-15): 256 threads ----
    const int ptid = tid - 256;                 // 0..255 for producers
    const int brow = (ptid & 255) >> 1;         // 0..127
    const int hs = ptid & 1;
    const int o = bx * 128 + brow;
    const int* crow = q2 + (size_t)o * 2048;
    const __half* Ag = g_xh + (size_t)(by * 128 + brow) * KPAD;
    const uint32_t a_off = (uint32_t)brow * (ROWP * 2) + (uint32_t)hs * 64;

    auto issueA = [&](int buf3, int kk) {
        uint32_t dst = sb + SM_A + buf3 * TILE_B + a_off;
        const char* src = (const char*)(Ag + kk + hs * 32);
#pragma unroll
        for (int u = 0; u < 4; u++)
            asm volatile("cp.async.cg.shared.global [%0], [%1], 16;"
                         :: "r"(dst + u * 16), "l"(src + u * 16) : "memory");
    };

    auto decodeSTS = [&](int j, uint4 C0, uint4 C1, float n) {
        uint32_t r[16];
        if (j < 128) {
            float n3 = n * 0.33333334f;
            __half h0 = __float2half_rn(-n),  h1 = __float2half_rn(-n3);
            __half h2 = __float2half_rn(n3),  h3 = __float2half_rn(n);
            uint32_t p01 = (uint32_t)__half_as_ushort(h0) | ((uint32_t)__half_as_ushort(h1) << 16);
            uint32_t p23 = (uint32_t)__half_as_ushort(h2) | ((uint32_t)__half_as_ushort(h3) << 16);
            uint32_t t_lo = __byte_perm(p01, p23, 0x6420);
            uint32_t t_hi = __byte_perm(p01, p23, 0x7531);
            uint32_t w[8] = {C0.x, C0.y, C0.z, C0.w, C1.x, C1.y, C1.z, C1.w};
#pragma unroll
            for (int i = 0; i < 8; i++) {
                uint32_t sel = selt[w[i] & 0xFF];
                uint32_t lo4 = __byte_perm(t_lo, 0u, sel);
                uint32_t hi4 = __byte_perm(t_hi, 0u, sel);
                r[2 * i]     = __byte_perm(lo4, hi4, 0x5140);
                r[2 * i + 1] = __byte_perm(lo4, hi4, 0x7362);
            }
        } else {
#pragma unroll
            for (int i = 0; i < 16; i++) r[i] = 0u;
            if (hs == 0) {
                r[0] = C0.x; r[1] = C0.y; r[2] = C0.z; r[3] = C0.w;
                r[4] = C1.x; r[5] = C1.y; r[6] = C1.z; r[7] = C1.w;
            }
        }
        char* dst = smem + SM_B + (j & 1) * TILE_B + brow * (ROWP * 2) + hs * 64;
        *(uint4*)(dst)      = make_uint4(r[0], r[1], r[2], r[3]);
        *(uint4*)(dst + 16) = make_uint4(r[4], r[5], r[6], r[7]);
        *(uint4*)(dst + 32) = make_uint4(r[8], r[9], r[10], r[11]);
        *(uint4*)(dst + 48) = make_uint4(r[12], r[13], r[14], r[15]);
    };

    auto loadCodes = [&](int j, uint4& C0, uint4& C1, float& n) {
        if (j < 128) {
            const uint4* p = (const uint4*)(crow + j * 16 + hs * 8);
            C0 = __ldg(p);
            C1 = __ldg(p + 1);
            n = load_norm(wn, o * 64 + (j >> 1), mode);
        } else if (hs == 0) {
            const float4* s = (const float4*)(lb + (size_t)o * 16);
            float4 f0 = __ldg(s), f1 = __ldg(s + 1), f2 = __ldg(s + 2), f3 = __ldg(s + 3);
            __half2 a0 = __floats2half2_rn(f0.x, f0.y), a1 = __floats2half2_rn(f0.z, f0.w);
            __half2 a2 = __floats2half2_rn(f1.x, f1.y), a3 = __floats2half2_rn(f1.z, f1.w);
            __half2 a4 = __floats2half2_rn(f2.x, f2.y), a5 = __floats2half2_rn(f2.z, f2.w);
            __half2 a6 = __floats2half2_rn(f3.x, f3.y), a7 = __floats2half2_rn(f3.z, f3.w);
            C0 = make_uint4(*(uint32_t*)&a0, *(uint32_t*)&a1, *(uint32_t*)&a2, *(uint32_t*)&a3);
            C1 = make_uint4(*(uint32_t*)&a4, *(uint32_t*)&a5, *(uint32_t*)&a6, *(uint32_t*)&a7);
        }
    };

    float acc[2][8][4];
#pragma unroll
    for (int mi = 0; mi < 2; mi++)
#pragma unroll
        for (int ni = 0; ni < 8; ni++)
#pragma unroll
            for (int r = 0; r < 4; r++) acc[mi][ni][r] = 0.f;

    // ---- prologue (producers fill B buf0, A bufs 0 & 1) ----
    uint4 C0 = {0, 0, 0, 0}, C1 = {0, 0, 0, 0};
    float cn = 0.f;
    if (!consumer) loadCodes(0, C0, C1, cn);
    __syncthreads();                              // sel table ready
    if (!consumer) {
        decodeSTS(0, C0, C1, cn);
        issueA(0, 0);  asm volatile("cp.async.commit_group;" ::: "memory");
        issueA(1, 64); asm volatile("cp.async.commit_group;" ::: "memory");
        loadCodes(1, C0, C1, cn);
        asm volatile("cp.async.wait_group 1;" ::: "memory");  // A buf0 landed
    }

    for (int it = 0; it < NITER; it++) {
        __syncthreads();   // B(it&1) decoded, A(it%3) landed

        if (consumer) {
            const uint32_t aBase = sb + SM_A + (uint32_t)(it % 3) * TILE_B;
            const uint32_t bBase = sb + SM_B + (uint32_t)(it & 1) * TILE_B;
#pragma unroll
            for (int ks = 0; ks < 4; ks++) {
                const uint32_t ksb = (uint32_t)ks * 32;
                uint32_t a[2][4];
                ldsm4(a[0][0], a[0][1], a[0][2], a[0][3], aBase + aFragOff[0] + ksb);
                ldsm4(a[1][0], a[1][1], a[1][2], a[1][3], aBase + aFragOff[1] + ksb);
#pragma unroll
                for (int ni2 = 0; ni2 < 4; ni2++) {
                    uint32_t b0, b1, b2, b3;
                    ldsm4(b0, b1, b2, b3, bBase + bFragOff[ni2] + ksb);
#pragma unroll
                    for (int mi = 0; mi < 2; mi++) {
                        mma16816(acc[mi][2 * ni2][0], acc[mi][2 * ni2][1],
                                 acc[mi][2 * ni2][2], acc[mi][2 * ni2][3],
                                 a[mi][0], a[mi][1], a[mi][2], a[mi][3], b0, b1);
                        mma16816(acc[mi][2 * ni2 + 1][0], acc[mi][2 * ni2 + 1][1],
                                 acc[mi][2 * ni2 + 1][2], acc[mi][2 * ni2 + 1][3],
                                 a[mi][0], a[mi][1], a[mi][2], a[mi][3], b2, b3);
                    }
                }
            }
        } else {
            if (it + 1 <= 128) decodeSTS(it + 1, C0, C1, cn);   // -> B (it+1)&1
            if (it + 2 <= 128) loadCodes(it + 2, C0, C1, cn);
            if (it + 2 < NITER) issueA((it + 2) % 3, (it + 2) * 64);
            asm volatile("cp.async.commit_group;" ::: "memory");
            asm volatile("cp.async.wait_group 1;" ::: "memory"); // A(it+1) landed
        }
    }

    // ---- epilogue (consumers only) ----
    if (consumer) {
        const int m0 = by * 128 + wm * 32 + fr;
        const int n00 = bx * 128 + wn2 * 64 + fc;
#pragma unroll
        for (int mi = 0; mi < 2; mi++) {
#pragma unroll
            for (int ni = 0; ni < 8; ni++) {
                int n = n00 + ni * 8;
                float b0 = __ldg(bias + n), b1 = __ldg(bias + n + 1);
                int mA = m0 + mi * 16;
                float2 v0 = {acc[mi][ni][0] + b0, acc[mi][ni][1] + b1};
                float2 v1 = {acc[mi][ni][2] + b0, acc[mi][ni][3] + b1};
                *(float2*)(out + (size_t)mA * OUT_F + n) = v0;
                *(float2*)(out + (size_t)(mA + 8) * OUT_F + n) = v1;
            }
        }
    } else {
        asm volatile("cp.async.wait_group 0;" ::: "memory");
    }
}

// ---------------- launch ----------------
extern "C" void kernel_launch(void* const* d_in, const int* in_sizes, int n_in,
                              void* d_out, int out_size) {
    int ix = -1, iq = -1, iwn = -1, ib = -1, ila = -1, ilb = -1;
    for (int i = 0; i < n_in; i++) {
        int s = in_sizes[i];
        if (s == TOKENS * IN_F)            ix = i;
        else if (s == OUT_F * IN_F / 4)    iq = i;
        else if (s == OUT_F * IN_F / 128)  iwn = i;
        else if (s == OUT_F)               ib = i;
        else if (s == 16 * IN_F)           { if (ila < 0) ila = i; else ilb = i; }
    }
    const float* x    = (const float*)d_in[ix];
    const int*   q2   = (const int*)d_in[iq];
    const void*  wn   = (const void*)d_in[iwn];
    const float* bias = (const float*)d_in[ib];
    const float* la   = (const float*)d_in[ila];
    const float* lb   = (const float*)d_in[ilb];
    float* out = (float*)d_out;

    qlora_prep<<<PREP_BLOCKS, 256>>>(x, la, wn);

    cudaFuncSetAttribute(qlora_gemm, cudaFuncAttributeMaxDynamicSharedMemorySize, GEMM_SMEM);
    qlora_gemm<<<dim3(64, 2), 512, GEMM_SMEM>>>(q2, wn, lb, bias, out);
}